// round 4
// baseline (speedup 1.0000x reference)
#include <cuda_runtime.h>
#include <math.h>
#include <stdint.h>

#define BB 4
#define TT 4096
#define DD 384
#define HD 64
#define BQ 64
#define BS 32

// Scratch (allocation-free)
__device__ float g_q[(size_t)BB * TT * HD];
__device__ float g_k[(size_t)BB * TT * HD];
__device__ float g_v[(size_t)BB * TT * DD];

__device__ __forceinline__ uint32_t tf32r(float f) {
    uint32_t u;
    asm("cvt.rna.tf32.f32 %0, %1;" : "=r"(u) : "f"(f));
    return u;
}

__device__ __forceinline__ void mma8(float* c, const uint32_t* a, uint32_t b0, uint32_t b1) {
    asm volatile(
        "mma.sync.aligned.m16n8k8.row.col.f32.tf32.tf32.f32 "
        "{%0,%1,%2,%3}, {%4,%5,%6,%7}, {%8,%9}, {%0,%1,%2,%3};\n"
        : "+f"(c[0]), "+f"(c[1]), "+f"(c[2]), "+f"(c[3])
        : "r"(a[0]), "r"(a[1]), "r"(a[2]), "r"(a[3]), "r"(b0), "r"(b1));
}

__device__ __forceinline__ void cp16(uint32_t dsh, const void* src) {
    asm volatile("cp.async.cg.shared.global [%0], [%1], 16;\n" :: "r"(dsh), "l"(src));
}

// ---------------- tf32 mma projection GEMM (unchanged from R3) ----------------
#define PK 384
#define PXS 36
#define PWS 36
#define PX_TILE (128 * PXS)
#define PW_TILE (64 * PWS)
#define PROJ_SMEM_FLOATS (2 * (PX_TILE + PW_TILE))
#define PROJ_SMEM_BYTES (PROJ_SMEM_FLOATS * 4)

__device__ __forceinline__ void proj_stage(float* sm, const float* X, const float* W,
                                           int bm, int bn, int k0, int buf, int tid)
{
    float* xb = sm + buf * (PX_TILE + PW_TILE);
    float* wb = xb + PX_TILE;
    uint32_t xbase = (uint32_t)__cvta_generic_to_shared(xb);
    uint32_t wbase = (uint32_t)__cvta_generic_to_shared(wb);
#pragma unroll
    for (int it = 0; it < 4; it++) {
        int i = tid + 256 * it;
        int r = i >> 3, c = (i & 7) << 2;
        cp16(xbase + (uint32_t)(r * PXS + c) * 4,
             X + (size_t)(bm * 128 + r) * PK + k0 + c);
    }
#pragma unroll
    for (int it = 0; it < 2; it++) {
        int i = tid + 256 * it;
        int r = i >> 3, c = (i & 7) << 2;
        cp16(wbase + (uint32_t)(r * PWS + c) * 4,
             W + (size_t)(bn * 64 + r) * PK + k0 + c);
    }
}

__global__ void __launch_bounds__(256) proj_gemm(
    const float* __restrict__ X, const float* __restrict__ W0,
    const float* __restrict__ W1, int N, int which_base)
{
    extern __shared__ float sm[];
    const int z = blockIdx.z;
    const float* W = z ? W1 : W0;
    const int which = which_base + z;
    float* __restrict__ Y = (which == 0) ? g_q : (which == 1) ? g_k : g_v;

    const int bm = blockIdx.y;
    const int bn = blockIdx.x;
    const int tid = threadIdx.x;
    const int w = tid >> 5, l = tid & 31;
    const int wm = w >> 1, wn = w & 1;
    const int g = l >> 2, q4 = l & 3;

    float c[2][4][4];
#pragma unroll
    for (int mt = 0; mt < 2; mt++)
#pragma unroll
        for (int j = 0; j < 4; j++) { c[mt][j][0] = c[mt][j][1] = c[mt][j][2] = c[mt][j][3] = 0.f; }

    proj_stage(sm, X, W, bm, bn, 0, 0, tid);
    asm volatile("cp.async.commit_group;\n");

    const int nC = PK / 32;
    for (int cc = 0; cc < nC; cc++) {
        __syncthreads();
        if (cc + 1 < nC) {
            proj_stage(sm, X, W, bm, bn, (cc + 1) * 32, (cc + 1) & 1, tid);
            asm volatile("cp.async.commit_group;\n");
            asm volatile("cp.async.wait_group 1;\n");
        } else {
            asm volatile("cp.async.wait_group 0;\n");
        }
        __syncthreads();

        const float* xb = sm + (cc & 1) * (PX_TILE + PW_TILE);
        const float* wb = xb + PX_TILE;
#pragma unroll
        for (int kk = 0; kk < 4; kk++) {
            const int k = kk * 8;
            uint32_t a[2][4];
#pragma unroll
            for (int mt = 0; mt < 2; mt++) {
                int r0 = wm * 32 + 16 * mt + g;
                a[mt][0] = tf32r(xb[r0 * PXS + k + q4]);
                a[mt][1] = tf32r(xb[(r0 + 8) * PXS + k + q4]);
                a[mt][2] = tf32r(xb[r0 * PXS + k + q4 + 4]);
                a[mt][3] = tf32r(xb[(r0 + 8) * PXS + k + q4 + 4]);
            }
            uint32_t bfr[4][2];
#pragma unroll
            for (int j = 0; j < 4; j++) {
                int n = wn * 32 + 8 * j + g;
                bfr[j][0] = tf32r(wb[n * PWS + k + q4]);
                bfr[j][1] = tf32r(wb[n * PWS + k + q4 + 4]);
            }
#pragma unroll
            for (int mt = 0; mt < 2; mt++)
#pragma unroll
                for (int j = 0; j < 4; j++)
                    mma8(c[mt][j], a[mt], bfr[j][0], bfr[j][1]);
        }
    }

#pragma unroll
    for (int mt = 0; mt < 2; mt++) {
        int r0 = bm * 128 + wm * 32 + 16 * mt + g;
#pragma unroll
        for (int j = 0; j < 4; j++) {
            int col = bn * 64 + wn * 32 + 8 * j + 2 * q4;
            *(float2*)&Y[(size_t)r0 * N + col] =
                make_float2(__uint_as_float(tf32r(c[mt][j][0])), __uint_as_float(tf32r(c[mt][j][1])));
            *(float2*)&Y[(size_t)(r0 + 8) * N + col] =
                make_float2(__uint_as_float(tf32r(c[mt][j][2])), __uint_as_float(tf32r(c[mt][j][3])));
        }
    }
}

// ---------------- tf32 flash attention: 384 threads, 12 warps (4 qw x 3 dw) ----------------
#define FTH 384
#define VS_STRIDE 392
#define KS_STRIDE 68
#define PS_STRIDE 36
#define VS_TILE (32 * VS_STRIDE)
#define KS_TILE (32 * KS_STRIDE)
#define VS_OFF 0
#define KS_OFF (2 * VS_TILE)
#define PS_OFF (KS_OFF + 2 * KS_TILE)
#define SMEM_FLOATS (PS_OFF + 12 * 16 * PS_STRIDE)
#define SMEM_BYTES (SMEM_FLOATS * 4)

__device__ __forceinline__ void stage_tile(float* sm, const float* Kb, const float* Vb,
                                           int s0, int buf, int tid)
{
    uint32_t vbase = (uint32_t)__cvta_generic_to_shared(sm + VS_OFF + buf * VS_TILE);
    uint32_t kbase = (uint32_t)__cvta_generic_to_shared(sm + KS_OFF + buf * KS_TILE);
#pragma unroll
    for (int it = 0; it < 2; it++) {              // K: 512 float4
        int i = tid + FTH * it;
        if (i < 512) {
            int r = i >> 4, c = (i & 15) << 2;
            cp16(kbase + (uint32_t)(r * KS_STRIDE + c) * 4, Kb + (size_t)(s0 + r) * HD + c);
        }
    }
#pragma unroll
    for (int it = 0; it < 8; it++) {              // V: 3072 float4 = 384*8
        int i = tid + FTH * it;
        int r = i / 96, c = (i % 96) << 2;
        cp16(vbase + (uint32_t)(r * VS_STRIDE + c) * 4, Vb + (size_t)(s0 + r) * DD + c);
    }
}

__global__ void __launch_bounds__(FTH, 1) flash2(float* __restrict__ O)
{
    extern __shared__ float sm[];
    const int b = blockIdx.y;
    const int qb = (int)gridDim.x - 1 - (int)blockIdx.x;
    const int q0 = qb * BQ;
    const int tid = threadIdx.x;
    const int w = tid >> 5, l = tid & 31;
    const int qw = w & 3, dw = w >> 2;     // qw 0..3 (16 rows), dw 0..2 (128 cols)
    const int g = l >> 2, q4 = l & 3;

    const float* Qb = g_q + ((size_t)b * TT + q0) * HD;
    const float* Kb = g_k + (size_t)b * TT * HD;
    const float* Vb = g_v + (size_t)b * TT * DD;

    float* Ps = sm + PS_OFF + w * (16 * PS_STRIDE);

    // Q fragments, register-resident for the whole kernel
    uint32_t qa[8][4];
    const int qr0 = qw * 16 + g;
#pragma unroll
    for (int kk = 0; kk < 8; kk++) {
        qa[kk][0] = __float_as_uint(Qb[(size_t)qr0 * HD + 8 * kk + q4]);
        qa[kk][1] = __float_as_uint(Qb[(size_t)(qr0 + 8) * HD + 8 * kk + q4]);
        qa[kk][2] = __float_as_uint(Qb[(size_t)qr0 * HD + 8 * kk + q4 + 4]);
        qa[kk][3] = __float_as_uint(Qb[(size_t)(qr0 + 8) * HD + 8 * kk + q4 + 4]);
    }

    float co[16][4];
#pragma unroll
    for (int j = 0; j < 16; j++) { co[j][0] = co[j][1] = co[j][2] = co[j][3] = 0.f; }
    float m0 = -1e30f, m1 = -1e30f, l0 = 0.f, l1 = 0.f;

    const int nT = (q0 + BQ) / BS;
    const int q_last = q0 + qw * 16 + 15;
    const int row0 = q0 + qw * 16 + g;
    const int row1 = row0 + 8;
    const int d0base = dw * 128;

    stage_tile(sm, Kb, Vb, 0, 0, tid);
    asm volatile("cp.async.commit_group;\n");

    for (int t = 0; t < nT; t++) {
        __syncthreads();
        if (t + 1 < nT) {
            stage_tile(sm, Kb, Vb, (t + 1) * BS, (t + 1) & 1, tid);
            asm volatile("cp.async.commit_group;\n");
            asm volatile("cp.async.wait_group 1;\n");
        } else {
            asm volatile("cp.async.wait_group 0;\n");
        }
        __syncthreads();

        const int s0 = t * BS;
        if (s0 <= q_last) {
            const float* Ks = sm + KS_OFF + (t & 1) * KS_TILE;
            const float* Vs = sm + VS_OFF + (t & 1) * VS_TILE;

            // ---- S = Q K^T (16x32 per warp; dw-redundant) ----
            float cs[4][4];
#pragma unroll
            for (int j = 0; j < 4; j++) { cs[j][0] = cs[j][1] = cs[j][2] = cs[j][3] = 0.f; }
#pragma unroll
            for (int kk = 0; kk < 8; kk++) {
#pragma unroll
                for (int j = 0; j < 4; j++) {
                    const float* kp = Ks + (8 * j + g) * KS_STRIDE + 8 * kk + q4;
                    mma8(cs[j], qa[kk], __float_as_uint(kp[0]), __float_as_uint(kp[4]));
                }
            }

            const bool needmask = (s0 + 31 > q0 + qw * 16);
            float mx0 = -1e30f, mx1 = -1e30f;
#pragma unroll
            for (int j = 0; j < 4; j++) {
                int c0 = s0 + 8 * j + 2 * q4;
                float s00 = cs[j][0] * 0.125f, s01 = cs[j][1] * 0.125f;
                float s10 = cs[j][2] * 0.125f, s11 = cs[j][3] * 0.125f;
                if (needmask) {
                    if (c0 > row0)     s00 = -1e30f;
                    if (c0 + 1 > row0) s01 = -1e30f;
                    if (c0 > row1)     s10 = -1e30f;
                    if (c0 + 1 > row1) s11 = -1e30f;
                }
                cs[j][0] = s00; cs[j][1] = s01; cs[j][2] = s10; cs[j][3] = s11;
                mx0 = fmaxf(mx0, fmaxf(s00, s01));
                mx1 = fmaxf(mx1, fmaxf(s10, s11));
            }
            mx0 = fmaxf(mx0, __shfl_xor_sync(0xffffffffu, mx0, 1, 4));
            mx0 = fmaxf(mx0, __shfl_xor_sync(0xffffffffu, mx0, 2, 4));
            mx1 = fmaxf(mx1, __shfl_xor_sync(0xffffffffu, mx1, 1, 4));
            mx1 = fmaxf(mx1, __shfl_xor_sync(0xffffffffu, mx1, 2, 4));

            float mn0 = fmaxf(m0, mx0), mn1 = fmaxf(m1, mx1);
            float cr0 = __expf(m0 - mn0), cr1 = __expf(m1 - mn1);
            m0 = mn0; m1 = mn1;

            float sum0 = 0.f, sum1 = 0.f;
#pragma unroll
            for (int j = 0; j < 4; j++) {
                float p00 = __expf(cs[j][0] - mn0), p01 = __expf(cs[j][1] - mn0);
                float p10 = __expf(cs[j][2] - mn1), p11 = __expf(cs[j][3] - mn1);
                sum0 += p00 + p01; sum1 += p10 + p11;
                *(float2*)&Ps[g * PS_STRIDE + 8 * j + 2 * q4] =
                    make_float2(__uint_as_float(tf32r(p00)), __uint_as_float(tf32r(p01)));
                *(float2*)&Ps[(g + 8) * PS_STRIDE + 8 * j + 2 * q4] =
                    make_float2(__uint_as_float(tf32r(p10)), __uint_as_float(tf32r(p11)));
            }
            sum0 += __shfl_xor_sync(0xffffffffu, sum0, 1, 4);
            sum0 += __shfl_xor_sync(0xffffffffu, sum0, 2, 4);
            sum1 += __shfl_xor_sync(0xffffffffu, sum1, 1, 4);
            sum1 += __shfl_xor_sync(0xffffffffu, sum1, 2, 4);
            l0 = l0 * cr0 + sum0;
            l1 = l1 * cr1 + sum1;

            // rescale only if some row's max actually moved (warp-uniform)
            if (!__all_sync(0xffffffffu, (cr0 == 1.f) & (cr1 == 1.f))) {
#pragma unroll
                for (int j = 0; j < 16; j++) {
                    co[j][0] *= cr0; co[j][1] *= cr0;
                    co[j][2] *= cr1; co[j][3] *= cr1;
                }
            }
            __syncwarp();

            // ---- O += P V (16 x 128 per warp) ----
#pragma unroll
            for (int kk = 0; kk < 4; kk++) {
                uint32_t a[4];
                a[0] = __float_as_uint(Ps[g * PS_STRIDE + 8 * kk + q4]);
                a[1] = __float_as_uint(Ps[(g + 8) * PS_STRIDE + 8 * kk + q4]);
                a[2] = __float_as_uint(Ps[g * PS_STRIDE + 8 * kk + q4 + 4]);
                a[3] = __float_as_uint(Ps[(g + 8) * PS_STRIDE + 8 * kk + q4 + 4]);
                const float* Vk = Vs + (8 * kk + q4) * VS_STRIDE + d0base + g;
#pragma unroll
                for (int j = 0; j < 16; j++) {
                    mma8(co[j], a, __float_as_uint(Vk[8 * j]),
                                   __float_as_uint(Vk[4 * VS_STRIDE + 8 * j]));
                }
            }
        }
    }

    const float i0 = 1.f / l0, i1 = 1.f / l1;
    float* O0 = O + ((size_t)b * TT + row0) * DD + d0base;
    float* O1 = O + ((size_t)b * TT + row1) * DD + d0base;
#pragma unroll
    for (int j = 0; j < 16; j++) {
        *(float2*)&O0[8 * j + 2 * q4] = make_float2(co[j][0] * i0, co[j][1] * i0);
        *(float2*)&O1[8 * j + 2 * q4] = make_float2(co[j][2] * i1, co[j][3] * i1);
    }
}

extern "C" void kernel_launch(void* const* d_in, const int* in_sizes, int n_in,
                              void* d_out, int out_size)
{
    const float* x  = (const float*)d_in[0];
    const float* Wk = (const float*)d_in[1];
    const float* Wq = (const float*)d_in[2];
    const float* Wv = (const float*)d_in[3];
    float* out = (float*)d_out;

    cudaFuncSetAttribute(proj_gemm, cudaFuncAttributeMaxDynamicSharedMemorySize, PROJ_SMEM_BYTES);
    proj_gemm<<<dim3(1, 128, 2), 256, PROJ_SMEM_BYTES>>>(x, Wq, Wk, HD, 0);
    proj_gemm<<<dim3(6, 128, 1), 256, PROJ_SMEM_BYTES>>>(x, Wv, Wv, DD, 2);

    cudaFuncSetAttribute(flash2, cudaFuncAttributeMaxDynamicSharedMemorySize, SMEM_BYTES);
    flash2<<<dim3(TT / BQ, BB), FTH, SMEM_BYTES>>>(out);
}

// round 5
// speedup vs baseline: 1.5345x; 1.5345x over previous
#include <cuda_runtime.h>
#include <cuda_fp16.h>
#include <math.h>
#include <stdint.h>

#define BB 4
#define TT 4096
#define DD 384
#define HD 64
#define BQ 64
#define BS 32

// Scratch (allocation-free). q/k: [b][t][d] half. vT: [b][d][t] half.
__device__ __half g_q[(size_t)BB * TT * HD];
__device__ __half g_k[(size_t)BB * TT * HD];
__device__ __half g_vT[(size_t)BB * DD * TT];

__device__ __forceinline__ uint32_t tf32r(float f) {
    uint32_t u;
    asm("cvt.rna.tf32.f32 %0, %1;" : "=r"(u) : "f"(f));
    return u;
}

__device__ __forceinline__ void mma8(float* c, const uint32_t* a, uint32_t b0, uint32_t b1) {
    asm volatile(
        "mma.sync.aligned.m16n8k8.row.col.f32.tf32.tf32.f32 "
        "{%0,%1,%2,%3}, {%4,%5,%6,%7}, {%8,%9}, {%0,%1,%2,%3};\n"
        : "+f"(c[0]), "+f"(c[1]), "+f"(c[2]), "+f"(c[3])
        : "r"(a[0]), "r"(a[1]), "r"(a[2]), "r"(a[3]), "r"(b0), "r"(b1));
}

__device__ __forceinline__ void mma16(float* c, const uint32_t* a, uint32_t b0, uint32_t b1) {
    asm volatile(
        "mma.sync.aligned.m16n8k16.row.col.f32.f16.f16.f32 "
        "{%0,%1,%2,%3}, {%4,%5,%6,%7}, {%8,%9}, {%0,%1,%2,%3};\n"
        : "+f"(c[0]), "+f"(c[1]), "+f"(c[2]), "+f"(c[3])
        : "r"(a[0]), "r"(a[1]), "r"(a[2]), "r"(a[3]), "r"(b0), "r"(b1));
}

__device__ __forceinline__ void cp16(uint32_t dsh, const void* src) {
    asm volatile("cp.async.cg.shared.global [%0], [%1], 16;\n" :: "r"(dsh), "l"(src));
}

// ---------------- tf32 mma projection GEMM, half outputs ----------------
#define PK 384
#define PXS 36
#define PWS 36
#define PX_TILE (128 * PXS)
#define PW_TILE (64 * PWS)
#define PROJ_SMEM_FLOATS (2 * (PX_TILE + PW_TILE))
#define PROJ_SMEM_BYTES (PROJ_SMEM_FLOATS * 4)
#define T2S 136   // transpose buffer stride in halfs (272B, 16B-aligned)

__device__ __forceinline__ void proj_stage(float* sm, const float* X, const float* W,
                                           int bm, int bn, int k0, int buf, int tid)
{
    float* xb = sm + buf * (PX_TILE + PW_TILE);
    float* wb = xb + PX_TILE;
    uint32_t xbase = (uint32_t)__cvta_generic_to_shared(xb);
    uint32_t wbase = (uint32_t)__cvta_generic_to_shared(wb);
#pragma unroll
    for (int it = 0; it < 4; it++) {
        int i = tid + 256 * it;
        int r = i >> 3, c = (i & 7) << 2;
        cp16(xbase + (uint32_t)(r * PXS + c) * 4,
             X + (size_t)(bm * 128 + r) * PK + k0 + c);
    }
#pragma unroll
    for (int it = 0; it < 2; it++) {
        int i = tid + 256 * it;
        int r = i >> 3, c = (i & 7) << 2;
        cp16(wbase + (uint32_t)(r * PWS + c) * 4,
             W + (size_t)(bn * 64 + r) * PK + k0 + c);
    }
}

__global__ void __launch_bounds__(256) proj_gemm(
    const float* __restrict__ X, const float* __restrict__ W0,
    const float* __restrict__ W1, int which_base)
{
    extern __shared__ float sm[];
    const int z = blockIdx.z;
    const float* W = z ? W1 : W0;
    const int which = which_base + z;

    const int bm = blockIdx.y;
    const int bn = blockIdx.x;
    const int tid = threadIdx.x;
    const int w = tid >> 5, l = tid & 31;
    const int wm = w >> 1, wn = w & 1;
    const int g = l >> 2, q4 = l & 3;

    float c[2][4][4];
#pragma unroll
    for (int mt = 0; mt < 2; mt++)
#pragma unroll
        for (int j = 0; j < 4; j++) { c[mt][j][0] = c[mt][j][1] = c[mt][j][2] = c[mt][j][3] = 0.f; }

    proj_stage(sm, X, W, bm, bn, 0, 0, tid);
    asm volatile("cp.async.commit_group;\n");

    const int nC = PK / 32;
    for (int cc = 0; cc < nC; cc++) {
        __syncthreads();
        if (cc + 1 < nC) {
            proj_stage(sm, X, W, bm, bn, (cc + 1) * 32, (cc + 1) & 1, tid);
            asm volatile("cp.async.commit_group;\n");
            asm volatile("cp.async.wait_group 1;\n");
        } else {
            asm volatile("cp.async.wait_group 0;\n");
        }
        __syncthreads();

        const float* xb = sm + (cc & 1) * (PX_TILE + PW_TILE);
        const float* wb = xb + PX_TILE;
#pragma unroll
        for (int kk = 0; kk < 4; kk++) {
            const int k = kk * 8;
            uint32_t a[2][4];
#pragma unroll
            for (int mt = 0; mt < 2; mt++) {
                int r0 = wm * 32 + 16 * mt + g;
                a[mt][0] = tf32r(xb[r0 * PXS + k + q4]);
                a[mt][1] = tf32r(xb[(r0 + 8) * PXS + k + q4]);
                a[mt][2] = tf32r(xb[r0 * PXS + k + q4 + 4]);
                a[mt][3] = tf32r(xb[(r0 + 8) * PXS + k + q4 + 4]);
            }
            uint32_t bfr[4][2];
#pragma unroll
            for (int j = 0; j < 4; j++) {
                int n = wn * 32 + 8 * j + g;
                bfr[j][0] = tf32r(wb[n * PWS + k + q4]);
                bfr[j][1] = tf32r(wb[n * PWS + k + q4 + 4]);
            }
#pragma unroll
            for (int mt = 0; mt < 2; mt++)
#pragma unroll
                for (int j = 0; j < 4; j++)
                    mma8(c[mt][j], a[mt], bfr[j][0], bfr[j][1]);
        }
    }

    if (which < 2) {
        // q/k: half2 coalesced writes, natural [t][d] layout
        __half* Y = (which == 0) ? g_q : g_k;
#pragma unroll
        for (int mt = 0; mt < 2; mt++) {
            int r0 = bm * 128 + wm * 32 + 16 * mt + g;
#pragma unroll
            for (int j = 0; j < 4; j++) {
                int col = wn * 32 + 8 * j + 2 * q4;
                *(__half2*)&Y[(size_t)r0 * HD + col] = __floats2half2_rn(c[mt][j][0], c[mt][j][1]);
                *(__half2*)&Y[(size_t)(r0 + 8) * HD + col] = __floats2half2_rn(c[mt][j][2], c[mt][j][3]);
            }
        }
    } else {
        // v: transpose via smem, write g_vT [b][d][t] coalesced
        __syncthreads();                        // staging buffers dead now
        __half* T2 = (__half*)sm;               // 64 x T2S halfs
#pragma unroll
        for (int mt = 0; mt < 2; mt++) {
            int r0 = wm * 32 + 16 * mt + g;
#pragma unroll
            for (int j = 0; j < 4; j++) {
                int col = wn * 32 + 8 * j + 2 * q4;
                T2[col * T2S + r0]           = __float2half_rn(c[mt][j][0]);
                T2[(col + 1) * T2S + r0]     = __float2half_rn(c[mt][j][1]);
                T2[col * T2S + r0 + 8]       = __float2half_rn(c[mt][j][2]);
                T2[(col + 1) * T2S + r0 + 8] = __float2half_rn(c[mt][j][3]);
            }
        }
        __syncthreads();
        const int bt0 = bm * 128;
        const int b = bt0 / TT, t0 = bt0 % TT;
        const int d = tid >> 2, qtr = tid & 3;  // 64 rows x 4 chunks of 32 halfs
        const uint4* srcv = (const uint4*)&T2[d * T2S + 32 * qtr];
        uint4* dstv = (uint4*)&g_vT[((size_t)b * DD + bn * 64 + d) * TT + t0 + 32 * qtr];
#pragma unroll
        for (int cch = 0; cch < 4; cch++) dstv[cch] = srcv[cch];
    }
}

// ---------------- fp16 mma flash attention: 256 threads, 8 warps (4 qw x 2 dw) ----------------
// smem strides in halfs
#define VST 40        // VT rows: 32 halfs + 8 pad (80B)
#define KST 72        // K rows: 64 halfs + 8 pad (144B)
#define PST 40
#define VT_TILE (384 * VST)
#define KS_TILE (32 * KST)
#define VT_OFF 0
#define KS_OFF (2 * VT_TILE)
#define PS_OFF (KS_OFF + 2 * KS_TILE)
#define SMEM_HALFS (PS_OFF + 8 * 16 * PST)
#define SMEM_BYTES (SMEM_HALFS * 2)

__device__ __forceinline__ void stage_tile(__half* smh, const __half* Kb, const __half* VTb,
                                           int s0, int buf, int tid)
{
    uint32_t vbase = (uint32_t)__cvta_generic_to_shared(smh + VT_OFF + buf * VT_TILE);
    uint32_t kbase = (uint32_t)__cvta_generic_to_shared(smh + KS_OFF + buf * KS_TILE);
    {   // K: 32 rows x 64 halfs = 256 x 16B
        int r = tid >> 3, c = tid & 7;
        cp16(kbase + (uint32_t)(r * KST + c * 8) * 2, Kb + (size_t)(s0 + r) * HD + c * 8);
    }
#pragma unroll
    for (int it = 0; it < 6; it++) {   // VT: 384 rows x 32 halfs = 1536 x 16B
        int i = tid + 256 * it;
        int r = i >> 2, c = i & 3;
        cp16(vbase + (uint32_t)(r * VST + c * 8) * 2, VTb + (size_t)r * TT + s0 + c * 8);
    }
}

__global__ void __launch_bounds__(256, 1) flash2(float* __restrict__ O)
{
    extern __shared__ __half smh[];
    const int b = blockIdx.y;
    const int qb = (int)gridDim.x - 1 - (int)blockIdx.x;
    const int q0 = qb * BQ;
    const int tid = threadIdx.x;
    const int w = tid >> 5, l = tid & 31;
    const int qw = w >> 1, dw = w & 1;
    const int g = l >> 2, q4 = l & 3;

    const __half* Qb = g_q + ((size_t)b * TT + q0) * HD;
    const __half* Kb = g_k + (size_t)b * TT * HD;
    const __half* VTb = g_vT + (size_t)b * DD * TT;

    __half* Ps = smh + PS_OFF + w * (16 * PST);

    // Q fragments: 4 k16-chunks x 4 regs, register-resident
    uint32_t qa[4][4];
    const int qr0 = qw * 16 + g;
#pragma unroll
    for (int kk = 0; kk < 4; kk++) {
        qa[kk][0] = *(const uint32_t*)&Qb[(size_t)qr0 * HD + 16 * kk + 2 * q4];
        qa[kk][1] = *(const uint32_t*)&Qb[(size_t)(qr0 + 8) * HD + 16 * kk + 2 * q4];
        qa[kk][2] = *(const uint32_t*)&Qb[(size_t)qr0 * HD + 16 * kk + 2 * q4 + 8];
        qa[kk][3] = *(const uint32_t*)&Qb[(size_t)(qr0 + 8) * HD + 16 * kk + 2 * q4 + 8];
    }

    float co[24][4];
#pragma unroll
    for (int j = 0; j < 24; j++) { co[j][0] = co[j][1] = co[j][2] = co[j][3] = 0.f; }
    float m0 = -1e30f, m1 = -1e30f, l0 = 0.f, l1 = 0.f;

    const int nT = (q0 + BQ) / BS;
    const int q_last = q0 + qw * 16 + 15;
    const int row0 = q0 + qw * 16 + g;
    const int row1 = row0 + 8;
    const int d0base = dw * 192;

    stage_tile(smh, Kb, VTb, 0, 0, tid);
    asm volatile("cp.async.commit_group;\n");

    for (int t = 0; t < nT; t++) {
        __syncthreads();
        if (t + 1 < nT) {
            stage_tile(smh, Kb, VTb, (t + 1) * BS, (t + 1) & 1, tid);
            asm volatile("cp.async.commit_group;\n");
            asm volatile("cp.async.wait_group 1;\n");
        } else {
            asm volatile("cp.async.wait_group 0;\n");
        }
        __syncthreads();

        const int s0 = t * BS;
        if (s0 <= q_last) {
            const __half* Ks = smh + KS_OFF + (t & 1) * KS_TILE;
            const __half* VTs = smh + VT_OFF + (t & 1) * VT_TILE;

            // ---- S = Q K^T : 4 k-chunks x 4 key-groups = 16 mma ----
            float cs[4][4];
#pragma unroll
            for (int j = 0; j < 4; j++) { cs[j][0] = cs[j][1] = cs[j][2] = cs[j][3] = 0.f; }
#pragma unroll
            for (int kk = 0; kk < 4; kk++) {
#pragma unroll
                for (int j = 0; j < 4; j++) {
                    const __half* kp = Ks + (8 * j + g) * KST + 16 * kk + 2 * q4;
                    mma16(cs[j], qa[kk], *(const uint32_t*)kp, *(const uint32_t*)(kp + 8));
                }
            }

            const bool needmask = (s0 + 31 > q0 + qw * 16);
            float mx0 = -1e30f, mx1 = -1e30f;
#pragma unroll
            for (int j = 0; j < 4; j++) {
                int c0 = s0 + 8 * j + 2 * q4;
                float s00 = cs[j][0] * 0.125f, s01 = cs[j][1] * 0.125f;
                float s10 = cs[j][2] * 0.125f, s11 = cs[j][3] * 0.125f;
                if (needmask) {
                    if (c0 > row0)     s00 = -1e30f;
                    if (c0 + 1 > row0) s01 = -1e30f;
                    if (c0 > row1)     s10 = -1e30f;
                    if (c0 + 1 > row1) s11 = -1e30f;
                }
                cs[j][0] = s00; cs[j][1] = s01; cs[j][2] = s10; cs[j][3] = s11;
                mx0 = fmaxf(mx0, fmaxf(s00, s01));
                mx1 = fmaxf(mx1, fmaxf(s10, s11));
            }
            mx0 = fmaxf(mx0, __shfl_xor_sync(0xffffffffu, mx0, 1, 4));
            mx0 = fmaxf(mx0, __shfl_xor_sync(0xffffffffu, mx0, 2, 4));
            mx1 = fmaxf(mx1, __shfl_xor_sync(0xffffffffu, mx1, 1, 4));
            mx1 = fmaxf(mx1, __shfl_xor_sync(0xffffffffu, mx1, 2, 4));

            float mn0 = fmaxf(m0, mx0), mn1 = fmaxf(m1, mx1);
            float cr0 = __expf(m0 - mn0), cr1 = __expf(m1 - mn1);
            m0 = mn0; m1 = mn1;

            float sum0 = 0.f, sum1 = 0.f;
#pragma unroll
            for (int j = 0; j < 4; j++) {
                float p00 = __expf(cs[j][0] - mn0), p01 = __expf(cs[j][1] - mn0);
                float p10 = __expf(cs[j][2] - mn1), p11 = __expf(cs[j][3] - mn1);
                sum0 += p00 + p01; sum1 += p10 + p11;
                *(__half2*)&Ps[g * PST + 8 * j + 2 * q4]       = __floats2half2_rn(p00, p01);
                *(__half2*)&Ps[(g + 8) * PST + 8 * j + 2 * q4] = __floats2half2_rn(p10, p11);
            }
            sum0 += __shfl_xor_sync(0xffffffffu, sum0, 1, 4);
            sum0 += __shfl_xor_sync(0xffffffffu, sum0, 2, 4);
            sum1 += __shfl_xor_sync(0xffffffffu, sum1, 1, 4);
            sum1 += __shfl_xor_sync(0xffffffffu, sum1, 2, 4);
            l0 = l0 * cr0 + sum0;
            l1 = l1 * cr1 + sum1;

            if (!__all_sync(0xffffffffu, (cr0 == 1.f) & (cr1 == 1.f))) {
#pragma unroll
                for (int j = 0; j < 24; j++) {
                    co[j][0] *= cr0; co[j][1] *= cr0;
                    co[j][2] *= cr1; co[j][3] *= cr1;
                }
            }
            __syncwarp();

            // ---- O += P V : 2 k-chunks x 24 d-groups = 48 mma ----
#pragma unroll
            for (int kc = 0; kc < 2; kc++) {
                uint32_t a[4];
                a[0] = *(const uint32_t*)&Ps[g * PST + 16 * kc + 2 * q4];
                a[1] = *(const uint32_t*)&Ps[(g + 8) * PST + 16 * kc + 2 * q4];
                a[2] = *(const uint32_t*)&Ps[g * PST + 16 * kc + 2 * q4 + 8];
                a[3] = *(const uint32_t*)&Ps[(g + 8) * PST + 16 * kc + 2 * q4 + 8];
                const __half* Vk = VTs + (size_t)(d0base + g) * VST + 16 * kc + 2 * q4;
#pragma unroll
                for (int j = 0; j < 24; j++) {
                    const __half* vp = Vk + 8 * j * VST;
                    mma16(co[j], a, *(const uint32_t*)vp, *(const uint32_t*)(vp + 8));
                }
            }
        }
    }

    const float i0 = 1.f / l0, i1 = 1.f / l1;
    float* O0 = O + ((size_t)b * TT + row0) * DD + d0base;
    float* O1 = O + ((size_t)b * TT + row1) * DD + d0base;
#pragma unroll
    for (int j = 0; j < 24; j++) {
        *(float2*)&O0[8 * j + 2 * q4] = make_float2(co[j][0] * i0, co[j][1] * i0);
        *(float2*)&O1[8 * j + 2 * q4] = make_float2(co[j][2] * i1, co[j][3] * i1);
    }
}

extern "C" void kernel_launch(void* const* d_in, const int* in_sizes, int n_in,
                              void* d_out, int out_size)
{
    const float* x  = (const float*)d_in[0];
    const float* Wk = (const float*)d_in[1];
    const float* Wq = (const float*)d_in[2];
    const float* Wv = (const float*)d_in[3];
    float* out = (float*)d_out;

    cudaFuncSetAttribute(proj_gemm, cudaFuncAttributeMaxDynamicSharedMemorySize, PROJ_SMEM_BYTES);
    proj_gemm<<<dim3(1, 128, 2), 256, PROJ_SMEM_BYTES>>>(x, Wq, Wk, 0);
    proj_gemm<<<dim3(6, 128, 1), 256, PROJ_SMEM_BYTES>>>(x, Wv, Wv, 2);

    cudaFuncSetAttribute(flash2, cudaFuncAttributeMaxDynamicSharedMemorySize, SMEM_BYTES);
    flash2<<<dim3(TT / BQ, BB), 256, SMEM_BYTES>>>(out);
}

// round 6
// speedup vs baseline: 1.7544x; 1.1433x over previous
#include <cuda_runtime.h>
#include <cuda_fp16.h>
#include <math.h>
#include <stdint.h>

#define BB 4
#define TT 4096
#define DD 384
#define HD 64
#define BQ 64
#define BS 64

// Scratch (allocation-free). q/k: [b][t][d] half (q pre-scaled by 0.125). vT: [b][d][t] half.
__device__ __half g_q[(size_t)BB * TT * HD];
__device__ __half g_k[(size_t)BB * TT * HD];
__device__ __half g_vT[(size_t)BB * DD * TT];

__device__ __forceinline__ uint32_t tf32r(float f) {
    uint32_t u;
    asm("cvt.rna.tf32.f32 %0, %1;" : "=r"(u) : "f"(f));
    return u;
}

__device__ __forceinline__ void mma8(float* c, const uint32_t* a, uint32_t b0, uint32_t b1) {
    asm volatile(
        "mma.sync.aligned.m16n8k8.row.col.f32.tf32.tf32.f32 "
        "{%0,%1,%2,%3}, {%4,%5,%6,%7}, {%8,%9}, {%0,%1,%2,%3};\n"
        : "+f"(c[0]), "+f"(c[1]), "+f"(c[2]), "+f"(c[3])
        : "r"(a[0]), "r"(a[1]), "r"(a[2]), "r"(a[3]), "r"(b0), "r"(b1));
}

__device__ __forceinline__ void mma16(float* c, const uint32_t* a, uint32_t b0, uint32_t b1) {
    asm volatile(
        "mma.sync.aligned.m16n8k16.row.col.f32.f16.f16.f32 "
        "{%0,%1,%2,%3}, {%4,%5,%6,%7}, {%8,%9}, {%0,%1,%2,%3};\n"
        : "+f"(c[0]), "+f"(c[1]), "+f"(c[2]), "+f"(c[3])
        : "r"(a[0]), "r"(a[1]), "r"(a[2]), "r"(a[3]), "r"(b0), "r"(b1));
}

__device__ __forceinline__ void cp16(uint32_t dsh, const void* src) {
    asm volatile("cp.async.cg.shared.global [%0], [%1], 16;\n" :: "r"(dsh), "l"(src));
}

// ---------------- tf32 mma projection GEMM, half outputs (q pre-scaled) ----------------
#define PK 384
#define PXS 36
#define PWS 36
#define PX_TILE (128 * PXS)
#define PW_TILE (64 * PWS)
#define PROJ_SMEM_FLOATS (2 * (PX_TILE + PW_TILE))
#define PROJ_SMEM_BYTES (PROJ_SMEM_FLOATS * 4)
#define T2S 136

__device__ __forceinline__ void proj_stage(float* sm, const float* X, const float* W,
                                           int bm, int bn, int k0, int buf, int tid)
{
    float* xb = sm + buf * (PX_TILE + PW_TILE);
    float* wb = xb + PX_TILE;
    uint32_t xbase = (uint32_t)__cvta_generic_to_shared(xb);
    uint32_t wbase = (uint32_t)__cvta_generic_to_shared(wb);
#pragma unroll
    for (int it = 0; it < 4; it++) {
        int i = tid + 256 * it;
        int r = i >> 3, c = (i & 7) << 2;
        cp16(xbase + (uint32_t)(r * PXS + c) * 4,
             X + (size_t)(bm * 128 + r) * PK + k0 + c);
    }
#pragma unroll
    for (int it = 0; it < 2; it++) {
        int i = tid + 256 * it;
        int r = i >> 3, c = (i & 7) << 2;
        cp16(wbase + (uint32_t)(r * PWS + c) * 4,
             W + (size_t)(bn * 64 + r) * PK + k0 + c);
    }
}

__global__ void __launch_bounds__(256) proj_gemm(
    const float* __restrict__ X, const float* __restrict__ W0,
    const float* __restrict__ W1, int which_base)
{
    extern __shared__ float sm[];
    const int z = blockIdx.z;
    const float* W = z ? W1 : W0;
    const int which = which_base + z;

    const int bm = blockIdx.y;
    const int bn = blockIdx.x;
    const int tid = threadIdx.x;
    const int w = tid >> 5, l = tid & 31;
    const int wm = w >> 1, wn = w & 1;
    const int g = l >> 2, q4 = l & 3;

    float c[2][4][4];
#pragma unroll
    for (int mt = 0; mt < 2; mt++)
#pragma unroll
        for (int j = 0; j < 4; j++) { c[mt][j][0] = c[mt][j][1] = c[mt][j][2] = c[mt][j][3] = 0.f; }

    proj_stage(sm, X, W, bm, bn, 0, 0, tid);
    asm volatile("cp.async.commit_group;\n");

    const int nC = PK / 32;
    for (int cc = 0; cc < nC; cc++) {
        __syncthreads();
        if (cc + 1 < nC) {
            proj_stage(sm, X, W, bm, bn, (cc + 1) * 32, (cc + 1) & 1, tid);
            asm volatile("cp.async.commit_group;\n");
            asm volatile("cp.async.wait_group 1;\n");
        } else {
            asm volatile("cp.async.wait_group 0;\n");
        }
        __syncthreads();

        const float* xb = sm + (cc & 1) * (PX_TILE + PW_TILE);
        const float* wb = xb + PX_TILE;
#pragma unroll
        for (int kk = 0; kk < 4; kk++) {
            const int k = kk * 8;
            uint32_t a[2][4];
#pragma unroll
            for (int mt = 0; mt < 2; mt++) {
                int r0 = wm * 32 + 16 * mt + g;
                a[mt][0] = tf32r(xb[r0 * PXS + k + q4]);
                a[mt][1] = tf32r(xb[(r0 + 8) * PXS + k + q4]);
                a[mt][2] = tf32r(xb[r0 * PXS + k + q4 + 4]);
                a[mt][3] = tf32r(xb[(r0 + 8) * PXS + k + q4 + 4]);
            }
            uint32_t bfr[4][2];
#pragma unroll
            for (int j = 0; j < 4; j++) {
                int n = wn * 32 + 8 * j + g;
                bfr[j][0] = tf32r(wb[n * PWS + k + q4]);
                bfr[j][1] = tf32r(wb[n * PWS + k + q4 + 4]);
            }
#pragma unroll
            for (int mt = 0; mt < 2; mt++)
#pragma unroll
                for (int j = 0; j < 4; j++)
                    mma8(c[mt][j], a[mt], bfr[j][0], bfr[j][1]);
        }
    }

    if (which < 2) {
        __half* Y = (which == 0) ? g_q : g_k;
        const float sc = (which == 0) ? 0.125f : 1.f;   // fold 1/sqrt(K) into q (exact)
#pragma unroll
        for (int mt = 0; mt < 2; mt++) {
            int r0 = bm * 128 + wm * 32 + 16 * mt + g;
#pragma unroll
            for (int j = 0; j < 4; j++) {
                int col = wn * 32 + 8 * j + 2 * q4;
                *(__half2*)&Y[(size_t)r0 * HD + col] =
                    __floats2half2_rn(c[mt][j][0] * sc, c[mt][j][1] * sc);
                *(__half2*)&Y[(size_t)(r0 + 8) * HD + col] =
                    __floats2half2_rn(c[mt][j][2] * sc, c[mt][j][3] * sc);
            }
        }
    } else {
        __syncthreads();
        __half* T2 = (__half*)sm;
#pragma unroll
        for (int mt = 0; mt < 2; mt++) {
            int r0 = wm * 32 + 16 * mt + g;
#pragma unroll
            for (int j = 0; j < 4; j++) {
                int col = wn * 32 + 8 * j + 2 * q4;
                T2[col * T2S + r0]           = __float2half_rn(c[mt][j][0]);
                T2[(col + 1) * T2S + r0]     = __float2half_rn(c[mt][j][1]);
                T2[col * T2S + r0 + 8]       = __float2half_rn(c[mt][j][2]);
                T2[(col + 1) * T2S + r0 + 8] = __float2half_rn(c[mt][j][3]);
            }
        }
        __syncthreads();
        const int bt0 = bm * 128;
        const int b = bt0 / TT, t0 = bt0 % TT;
        const int d = tid >> 2, qtr = tid & 3;
        const uint4* srcv = (const uint4*)&T2[d * T2S + 32 * qtr];
        uint4* dstv = (uint4*)&g_vT[((size_t)b * DD + bn * 64 + d) * TT + t0 + 32 * qtr];
#pragma unroll
        for (int cch = 0; cch < 4; cch++) dstv[cch] = srcv[cch];
    }
}

// ---------------- fp16 mma flash attention: BS=64 tiles, 8 warps (4 qw x 2 dw) ----------------
#define VST 72        // VT rows: 64 halfs + 8 pad (144B)
#define KST 72        // K rows: 64 halfs + 8 pad
#define PST 72        // P rows: 64 halfs + 8 pad
#define VT_TILE (384 * VST)
#define KS_TILE (64 * KST)
#define VT_OFF 0
#define KS_OFF (2 * VT_TILE)
#define PS_OFF (KS_OFF + 2 * KS_TILE)
#define SMEM_HALFS (PS_OFF + 8 * 16 * PST)
#define SMEM_BYTES (SMEM_HALFS * 2)

__device__ __forceinline__ void stage_tile(__half* smh, const __half* Kb, const __half* VTb,
                                           int s0, int buf, int tid)
{
    uint32_t vbase = (uint32_t)__cvta_generic_to_shared(smh + VT_OFF + buf * VT_TILE);
    uint32_t kbase = (uint32_t)__cvta_generic_to_shared(smh + KS_OFF + buf * KS_TILE);
#pragma unroll
    for (int it = 0; it < 2; it++) {   // K: 64 rows x 64 halfs = 512 x 16B
        int i = tid + 256 * it;
        int r = i >> 3, c = i & 7;
        cp16(kbase + (uint32_t)(r * KST + c * 8) * 2, Kb + (size_t)(s0 + r) * HD + c * 8);
    }
#pragma unroll
    for (int it = 0; it < 12; it++) {  // VT: 384 rows x 64 halfs = 3072 x 16B
        int i = tid + 256 * it;
        int r = i >> 3, c = i & 7;
        cp16(vbase + (uint32_t)(r * VST + c * 8) * 2, VTb + (size_t)r * TT + s0 + c * 8);
    }
}

__global__ void __launch_bounds__(256, 1) flash2(float* __restrict__ O)
{
    extern __shared__ __half smh[];
    const int b = blockIdx.y;
    const int qb = (int)gridDim.x - 1 - (int)blockIdx.x;
    const int q0 = qb * BQ;
    const int tid = threadIdx.x;
    const int w = tid >> 5, l = tid & 31;
    const int qw = w >> 1, dw = w & 1;
    const int g = l >> 2, q4 = l & 3;

    const __half* Qb = g_q + ((size_t)b * TT + q0) * HD;
    const __half* Kb = g_k + (size_t)b * TT * HD;
    const __half* VTb = g_vT + (size_t)b * DD * TT;

    __half* Ps = smh + PS_OFF + w * (16 * PST);

    uint32_t qa[4][4];
    const int qr0 = qw * 16 + g;
#pragma unroll
    for (int kk = 0; kk < 4; kk++) {
        qa[kk][0] = *(const uint32_t*)&Qb[(size_t)qr0 * HD + 16 * kk + 2 * q4];
        qa[kk][1] = *(const uint32_t*)&Qb[(size_t)(qr0 + 8) * HD + 16 * kk + 2 * q4];
        qa[kk][2] = *(const uint32_t*)&Qb[(size_t)qr0 * HD + 16 * kk + 2 * q4 + 8];
        qa[kk][3] = *(const uint32_t*)&Qb[(size_t)(qr0 + 8) * HD + 16 * kk + 2 * q4 + 8];
    }

    float co[24][4];
#pragma unroll
    for (int j = 0; j < 24; j++) { co[j][0] = co[j][1] = co[j][2] = co[j][3] = 0.f; }
    float m0 = -1e30f, m1 = -1e30f, l0 = 0.f, l1 = 0.f;

    const int nT = (q0 + BQ) / BS;   // = qb + 1
    const int q_last = q0 + qw * 16 + 15;
    const int row0 = q0 + qw * 16 + g;
    const int row1 = row0 + 8;
    const int d0base = dw * 192;

    stage_tile(smh, Kb, VTb, 0, 0, tid);
    asm volatile("cp.async.commit_group;\n");

    for (int t = 0; t < nT; t++) {
        __syncthreads();
        if (t + 1 < nT) {
            stage_tile(smh, Kb, VTb, (t + 1) * BS, (t + 1) & 1, tid);
            asm volatile("cp.async.commit_group;\n");
            asm volatile("cp.async.wait_group 1;\n");
        } else {
            asm volatile("cp.async.wait_group 0;\n");
        }
        __syncthreads();

        const int s0 = t * BS;
        if (s0 <= q_last) {
            const __half* Ks = smh + KS_OFF + (t & 1) * KS_TILE;
            const __half* VTs = smh + VT_OFF + (t & 1) * VT_TILE;

            // ---- S = Q K^T : 4 k-chunks x 8 key-groups = 32 mma ----
            float cs[8][4];
#pragma unroll
            for (int j = 0; j < 8; j++) { cs[j][0] = cs[j][1] = cs[j][2] = cs[j][3] = 0.f; }
#pragma unroll
            for (int kk = 0; kk < 4; kk++) {
#pragma unroll
                for (int j = 0; j < 8; j++) {
                    const __half* kp = Ks + (8 * j + g) * KST + 16 * kk + 2 * q4;
                    mma16(cs[j], qa[kk], *(const uint32_t*)kp, *(const uint32_t*)(kp + 8));
                }
            }

            const bool needmask = (s0 + BS - 1 > q0 + qw * 16);
            float mx0 = -1e30f, mx1 = -1e30f;
#pragma unroll
            for (int j = 0; j < 8; j++) {
                int c0 = s0 + 8 * j + 2 * q4;
                float s00 = cs[j][0], s01 = cs[j][1];
                float s10 = cs[j][2], s11 = cs[j][3];
                if (needmask) {
                    if (c0 > row0)     s00 = -1e30f;
                    if (c0 + 1 > row0) s01 = -1e30f;
                    if (c0 > row1)     s10 = -1e30f;
                    if (c0 + 1 > row1) s11 = -1e30f;
                }
                cs[j][0] = s00; cs[j][1] = s01; cs[j][2] = s10; cs[j][3] = s11;
                mx0 = fmaxf(mx0, fmaxf(s00, s01));
                mx1 = fmaxf(mx1, fmaxf(s10, s11));
            }
            mx0 = fmaxf(mx0, __shfl_xor_sync(0xffffffffu, mx0, 1, 4));
            mx0 = fmaxf(mx0, __shfl_xor_sync(0xffffffffu, mx0, 2, 4));
            mx1 = fmaxf(mx1, __shfl_xor_sync(0xffffffffu, mx1, 1, 4));
            mx1 = fmaxf(mx1, __shfl_xor_sync(0xffffffffu, mx1, 2, 4));

            float mn0 = fmaxf(m0, mx0), mn1 = fmaxf(m1, mx1);
            float cr0 = __expf(m0 - mn0), cr1 = __expf(m1 - mn1);
            m0 = mn0; m1 = mn1;

            float sum0 = 0.f, sum1 = 0.f;
#pragma unroll
            for (int j = 0; j < 8; j++) {
                float p00 = __expf(cs[j][0] - mn0), p01 = __expf(cs[j][1] - mn0);
                float p10 = __expf(cs[j][2] - mn1), p11 = __expf(cs[j][3] - mn1);
                sum0 += p00 + p01; sum1 += p10 + p11;
                *(__half2*)&Ps[g * PST + 8 * j + 2 * q4]       = __floats2half2_rn(p00, p01);
                *(__half2*)&Ps[(g + 8) * PST + 8 * j + 2 * q4] = __floats2half2_rn(p10, p11);
            }
            sum0 += __shfl_xor_sync(0xffffffffu, sum0, 1, 4);
            sum0 += __shfl_xor_sync(0xffffffffu, sum0, 2, 4);
            sum1 += __shfl_xor_sync(0xffffffffu, sum1, 1, 4);
            sum1 += __shfl_xor_sync(0xffffffffu, sum1, 2, 4);
            l0 = l0 * cr0 + sum0;
            l1 = l1 * cr1 + sum1;

            if (!__all_sync(0xffffffffu, (cr0 == 1.f) & (cr1 == 1.f))) {
#pragma unroll
                for (int j = 0; j < 24; j++) {
                    co[j][0] *= cr0; co[j][1] *= cr0;
                    co[j][2] *= cr1; co[j][3] *= cr1;
                }
            }
            __syncwarp();

            // ---- O += P V : 4 k-chunks x 24 d-groups = 96 mma ----
#pragma unroll
            for (int kc = 0; kc < 4; kc++) {
                uint32_t a[4];
                a[0] = *(const uint32_t*)&Ps[g * PST + 16 * kc + 2 * q4];
                a[1] = *(const uint32_t*)&Ps[(g + 8) * PST + 16 * kc + 2 * q4];
                a[2] = *(const uint32_t*)&Ps[g * PST + 16 * kc + 2 * q4 + 8];
                a[3] = *(const uint32_t*)&Ps[(g + 8) * PST + 16 * kc + 2 * q4 + 8];
                const __half* Vk = VTs + (size_t)(d0base + g) * VST + 16 * kc + 2 * q4;
#pragma unroll
                for (int j = 0; j < 24; j++) {
                    const __half* vp = Vk + 8 * j * VST;
                    mma16(co[j], a, *(const uint32_t*)vp, *(const uint32_t*)(vp + 8));
                }
            }
        }
    }

    const float i0 = 1.f / l0, i1 = 1.f / l1;
    float* O0 = O + ((size_t)b * TT + row0) * DD + d0base;
    float* O1 = O + ((size_t)b * TT + row1) * DD + d0base;
#pragma unroll
    for (int j = 0; j < 24; j++) {
        *(float2*)&O0[8 * j + 2 * q4] = make_float2(co[j][0] * i0, co[j][1] * i0);
        *(float2*)&O1[8 * j + 2 * q4] = make_float2(co[j][2] * i1, co[j][3] * i1);
    }
}

extern "C" void kernel_launch(void* const* d_in, const int* in_sizes, int n_in,
                              void* d_out, int out_size)
{
    const float* x  = (const float*)d_in[0];
    const float* Wk = (const float*)d_in[1];
    const float* Wq = (const float*)d_in[2];
    const float* Wv = (const float*)d_in[3];
    float* out = (float*)d_out;

    cudaFuncSetAttribute(proj_gemm, cudaFuncAttributeMaxDynamicSharedMemorySize, PROJ_SMEM_BYTES);
    proj_gemm<<<dim3(1, 128, 2), 256, PROJ_SMEM_BYTES>>>(x, Wq, Wk, 0);
    proj_gemm<<<dim3(6, 128, 1), 256, PROJ_SMEM_BYTES>>>(x, Wv, Wv, 2);

    cudaFuncSetAttribute(flash2, cudaFuncAttributeMaxDynamicSharedMemorySize, SMEM_BYTES);
    flash2<<<dim3(TT / BQ, BB), 256, SMEM_BYTES>>>(out);
}

// round 9
// speedup vs baseline: 1.8708x; 1.0664x over previous
#include <cuda_runtime.h>
#include <cuda_fp16.h>
#include <math.h>
#include <stdint.h>

#define BB 4
#define TT 4096
#define DD 384
#define HD 64
#define BQ 64
#define BS 64

// Scratch (allocation-free). NEVER reference these from host code (device-symbol
// addresses are invalid in host context; on GB300/ATS it silently writes host mem).
__device__ __half g_xh[(size_t)BB * TT * DD];
__device__ __half g_wq[(size_t)HD * DD];
__device__ __half g_wk[(size_t)HD * DD];
__device__ __half g_wv[(size_t)DD * DD];
__device__ __half g_q[(size_t)BB * TT * HD];     // pre-scaled by 0.125 (via Wq)
__device__ __half g_k[(size_t)BB * TT * HD];
__device__ __half g_vT[(size_t)BB * DD * TT];    // [b][d][t]

__device__ __forceinline__ void mma16(float* c, const uint32_t* a, uint32_t b0, uint32_t b1) {
    asm volatile(
        "mma.sync.aligned.m16n8k16.row.col.f32.f16.f16.f32 "
        "{%0,%1,%2,%3}, {%4,%5,%6,%7}, {%8,%9}, {%0,%1,%2,%3};\n"
        : "+f"(c[0]), "+f"(c[1]), "+f"(c[2]), "+f"(c[3])
        : "r"(a[0]), "r"(a[1]), "r"(a[2]), "r"(a[3]), "r"(b0), "r"(b1));
}

__device__ __forceinline__ void ldsm4(uint32_t& r0, uint32_t& r1, uint32_t& r2, uint32_t& r3,
                                      uint32_t addr) {
    asm volatile("ldmatrix.sync.aligned.m8n8.x4.shared.b16 {%0,%1,%2,%3}, [%4];"
                 : "=r"(r0), "=r"(r1), "=r"(r2), "=r"(r3) : "r"(addr) : "memory");
}

__device__ __forceinline__ void cp16(uint32_t dsh, const void* src) {
    asm volatile("cp.async.cg.shared.global [%0], [%1], 16;\n" :: "r"(dsh), "l"(src));
}

// ---------------- fp32 -> fp16 conversion; destination resolved in DEVICE code ----------------
__global__ void __launch_bounds__(256) to_half(const float* __restrict__ s,
                                               int n4, float sc, int which)
{
    __half* d = (which == 0) ? g_xh : (which == 1) ? g_wq : (which == 2) ? g_wk : g_wv;
    int i = blockIdx.x * 256 + threadIdx.x;
    if (i < n4) {
        float4 v = ((const float4*)s)[i];
        __half2 h0 = __floats2half2_rn(v.x * sc, v.y * sc);
        __half2 h1 = __floats2half2_rn(v.z * sc, v.w * sc);
        uint2 o;
        o.x = *(uint32_t*)&h0;
        o.y = *(uint32_t*)&h1;
        ((uint2*)d)[i] = o;
    }
}

// ---------------- fp16 mma projection GEMM ----------------
#define XS 72                        // X tile row stride (halfs), 144B
#define WS 72
#define X_TILE (128 * XS)
#define W_TILE (64 * WS)
#define PROJ_SMEM_HALFS (2 * (X_TILE + W_TILE))
#define PROJ_SMEM_BYTES (PROJ_SMEM_HALFS * 2)
#define T2S 136

__device__ __forceinline__ void proj_stage(__half* smp, const __half* X, const __half* W,
                                           int bm, int bn, int k0, int buf, int tid)
{
    __half* xb = smp + buf * (X_TILE + W_TILE);
    __half* wb = xb + X_TILE;
    uint32_t xbase = (uint32_t)__cvta_generic_to_shared(xb);
    uint32_t wbase = (uint32_t)__cvta_generic_to_shared(wb);
#pragma unroll
    for (int it = 0; it < 4; it++) {             // X: 128 rows x 64 halfs = 1024 x 16B
        int i = tid + 256 * it;
        int r = i >> 3, c = i & 7;
        cp16(xbase + (uint32_t)(r * XS + c * 8) * 2,
             X + (size_t)(bm * 128 + r) * DD + k0 + c * 8);
    }
#pragma unroll
    for (int it = 0; it < 2; it++) {             // W: 64 rows x 64 halfs = 512 x 16B
        int i = tid + 256 * it;
        int r = i >> 3, c = i & 7;
        cp16(wbase + (uint32_t)(r * WS + c * 8) * 2,
             W + (size_t)(bn * 64 + r) * DD + k0 + c * 8);
    }
}

__global__ void __launch_bounds__(256) proj_gemm(int which_base)
{
    extern __shared__ __half smp[];
    const int z = blockIdx.z;
    const int which = which_base + z;
    const __half* X = g_xh;
    const __half* W = (which == 0) ? g_wq : (which == 1) ? g_wk : g_wv;

    const int bm = blockIdx.y;
    const int bn = blockIdx.x;
    const int tid = threadIdx.x;
    const int w = tid >> 5, l = tid & 31;
    const int wm = w >> 1, wn = w & 1;
    const int g = l >> 2, q4 = l & 3;

    float c[2][4][4];
#pragma unroll
    for (int mt = 0; mt < 2; mt++)
#pragma unroll
        for (int j = 0; j < 4; j++) { c[mt][j][0] = c[mt][j][1] = c[mt][j][2] = c[mt][j][3] = 0.f; }

    proj_stage(smp, X, W, bm, bn, 0, 0, tid);
    asm volatile("cp.async.commit_group;\n");

    const int nC = DD / 64;   // 6
    for (int cc = 0; cc < nC; cc++) {
        __syncthreads();
        if (cc + 1 < nC) {
            proj_stage(smp, X, W, bm, bn, (cc + 1) * 64, (cc + 1) & 1, tid);
            asm volatile("cp.async.commit_group;\n");
            asm volatile("cp.async.wait_group 1;\n");
        } else {
            asm volatile("cp.async.wait_group 0;\n");
        }
        __syncthreads();

        const __half* xb = smp + (cc & 1) * (X_TILE + W_TILE);
        const __half* wb = xb + X_TILE;
#pragma unroll
        for (int kk = 0; kk < 4; kk++) {
            const int k = kk * 16;
            uint32_t a[2][4];
#pragma unroll
            for (int mt = 0; mt < 2; mt++) {
                int r0 = wm * 32 + 16 * mt + g;
                a[mt][0] = *(const uint32_t*)&xb[r0 * XS + k + 2 * q4];
                a[mt][1] = *(const uint32_t*)&xb[(r0 + 8) * XS + k + 2 * q4];
                a[mt][2] = *(const uint32_t*)&xb[r0 * XS + k + 2 * q4 + 8];
                a[mt][3] = *(const uint32_t*)&xb[(r0 + 8) * XS + k + 2 * q4 + 8];
            }
#pragma unroll
            for (int j = 0; j < 4; j++) {
                int n = wn * 32 + 8 * j + g;
                uint32_t b0 = *(const uint32_t*)&wb[n * WS + k + 2 * q4];
                uint32_t b1 = *(const uint32_t*)&wb[n * WS + k + 2 * q4 + 8];
#pragma unroll
                for (int mt = 0; mt < 2; mt++) mma16(c[mt][j], a[mt], b0, b1);
            }
        }
    }

    if (which < 2) {
        __half* Y = (which == 0) ? g_q : g_k;
#pragma unroll
        for (int mt = 0; mt < 2; mt++) {
            int r0 = bm * 128 + wm * 32 + 16 * mt + g;
#pragma unroll
            for (int j = 0; j < 4; j++) {
                int col = wn * 32 + 8 * j + 2 * q4;
                *(__half2*)&Y[(size_t)r0 * HD + col] = __floats2half2_rn(c[mt][j][0], c[mt][j][1]);
                *(__half2*)&Y[(size_t)(r0 + 8) * HD + col] = __floats2half2_rn(c[mt][j][2], c[mt][j][3]);
            }
        }
    } else {
        __syncthreads();
        __half* T2 = smp;
#pragma unroll
        for (int mt = 0; mt < 2; mt++) {
            int r0 = wm * 32 + 16 * mt + g;
#pragma unroll
            for (int j = 0; j < 4; j++) {
                int col = wn * 32 + 8 * j + 2 * q4;
                T2[col * T2S + r0]           = __float2half_rn(c[mt][j][0]);
                T2[(col + 1) * T2S + r0]     = __float2half_rn(c[mt][j][1]);
                T2[col * T2S + r0 + 8]       = __float2half_rn(c[mt][j][2]);
                T2[(col + 1) * T2S + r0 + 8] = __float2half_rn(c[mt][j][3]);
            }
        }
        __syncthreads();
        const int bt0 = bm * 128;
        const int b = bt0 / TT, t0 = bt0 % TT;
        const int d = tid >> 2, qtr = tid & 3;
        const uint4* srcv = (const uint4*)&T2[d * T2S + 32 * qtr];
        uint4* dstv = (uint4*)&g_vT[((size_t)b * DD + bn * 64 + d) * TT + t0 + 32 * qtr];
#pragma unroll
        for (int cch = 0; cch < 4; cch++) dstv[cch] = srcv[cch];
    }
}

// ---------------- fp16 mma flash attention: BS=64, ldmatrix, 8 warps ----------------
#define VST 72
#define KST 72
#define PST 72
#define VT_TILE (384 * VST)
#define KS_TILE (64 * KST)
#define VT_OFF 0
#define KS_OFF (2 * VT_TILE)
#define PS_OFF (KS_OFF + 2 * KS_TILE)
#define SMEM_HALFS (PS_OFF + 8 * 16 * PST)
#define SMEM_BYTES (SMEM_HALFS * 2)

__device__ __forceinline__ void stage_tile(__half* smh, const __half* Kb, const __half* VTb,
                                           int s0, int buf, int tid)
{
    uint32_t vbase = (uint32_t)__cvta_generic_to_shared(smh + VT_OFF + buf * VT_TILE);
    uint32_t kbase = (uint32_t)__cvta_generic_to_shared(smh + KS_OFF + buf * KS_TILE);
#pragma unroll
    for (int it = 0; it < 2; it++) {
        int i = tid + 256 * it;
        int r = i >> 3, c = i & 7;
        cp16(kbase + (uint32_t)(r * KST + c * 8) * 2, Kb + (size_t)(s0 + r) * HD + c * 8);
    }
#pragma unroll
    for (int it = 0; it < 12; it++) {
        int i = tid + 256 * it;
        int r = i >> 3, c = i & 7;
        cp16(vbase + (uint32_t)(r * VST + c * 8) * 2, VTb + (size_t)r * TT + s0 + c * 8);
    }
}

__global__ void __launch_bounds__(256, 1) flash2(float* __restrict__ O)
{
    extern __shared__ __half smh[];
    const int b = blockIdx.y;
    const int qb = (int)gridDim.x - 1 - (int)blockIdx.x;
    const int q0 = qb * BQ;
    const int tid = threadIdx.x;
    const int w = tid >> 5, l = tid & 31;
    const int qw = w >> 1, dw = w & 1;
    const int g = l >> 2, q4 = l & 3;

    const __half* Qb = g_q + ((size_t)b * TT + q0) * HD;
    const __half* Kb = g_k + (size_t)b * TT * HD;
    const __half* VTb = g_vT + (size_t)b * DD * TT;

    __half* Ps = smh + PS_OFF + w * (16 * PST);

    // ldmatrix lane geometry
    const int mm = l >> 3;
    const int rowB = (l & 7) + ((mm >> 1) << 3);
    const int colB = (mm & 1) << 3;
    const int rowA = (l & 7) + ((mm & 1) << 3);
    const int colA = (mm >> 1) << 3;
    const uint32_t smb = (uint32_t)__cvta_generic_to_shared(smh);
    const uint32_t psa = smb + (uint32_t)(PS_OFF + w * 16 * PST + rowA * PST + colA) * 2;

    uint32_t qa[4][4];
    const int qr0 = qw * 16 + g;
#pragma unroll
    for (int kk = 0; kk < 4; kk++) {
        qa[kk][0] = *(const uint32_t*)&Qb[(size_t)qr0 * HD + 16 * kk + 2 * q4];
        qa[kk][1] = *(const uint32_t*)&Qb[(size_t)(qr0 + 8) * HD + 16 * kk + 2 * q4];
        qa[kk][2] = *(const uint32_t*)&Qb[(size_t)qr0 * HD + 16 * kk + 2 * q4 + 8];
        qa[kk][3] = *(const uint32_t*)&Qb[(size_t)(qr0 + 8) * HD + 16 * kk + 2 * q4 + 8];
    }

    float co[24][4];
#pragma unroll
    for (int j = 0; j < 24; j++) { co[j][0] = co[j][1] = co[j][2] = co[j][3] = 0.f; }
    float m0 = -1e30f, m1 = -1e30f, l0 = 0.f, l1 = 0.f;

    const int nT = (q0 + BQ) / BS;
    const int q_last = q0 + qw * 16 + 15;
    const int row0 = q0 + qw * 16 + g;
    const int row1 = row0 + 8;
    const int d0base = dw * 192;

    stage_tile(smh, Kb, VTb, 0, 0, tid);
    asm volatile("cp.async.commit_group;\n");

    for (int t = 0; t < nT; t++) {
        __syncthreads();
        if (t + 1 < nT) {
            stage_tile(smh, Kb, VTb, (t + 1) * BS, (t + 1) & 1, tid);
            asm volatile("cp.async.commit_group;\n");
            asm volatile("cp.async.wait_group 1;\n");
        } else {
            asm volatile("cp.async.wait_group 0;\n");
        }
        __syncthreads();

        const int s0 = t * BS;
        if (s0 <= q_last) {
            const uint32_t ksb = smb + (uint32_t)(KS_OFF + (t & 1) * KS_TILE + rowB * KST + colB) * 2;
            const uint32_t vtb = smb + (uint32_t)(VT_OFF + (t & 1) * VT_TILE
                                                  + (d0base + rowB) * VST + colB) * 2;

            // ---- S = Q K^T : 16 ldsm4 + 32 mma ----
            float cs[8][4];
#pragma unroll
            for (int j = 0; j < 8; j++) { cs[j][0] = cs[j][1] = cs[j][2] = cs[j][3] = 0.f; }
#pragma unroll
            for (int kk = 0; kk < 4; kk++) {
#pragma unroll
                for (int jp = 0; jp < 4; jp++) {
                    uint32_t b0, b1, b2, b3;
                    ldsm4(b0, b1, b2, b3, ksb + (uint32_t)(jp * 16 * KST + kk * 16) * 2);
                    mma16(cs[2 * jp], qa[kk], b0, b1);
                    mma16(cs[2 * jp + 1], qa[kk], b2, b3);
                }
            }

            const bool needmask = (s0 + BS - 1 > q0 + qw * 16);
            float mx0 = -1e30f, mx1 = -1e30f;
#pragma unroll
            for (int j = 0; j < 8; j++) {
                int c0 = s0 + 8 * j + 2 * q4;
                float s00 = cs[j][0], s01 = cs[j][1];
                float s10 = cs[j][2], s11 = cs[j][3];
                if (needmask) {
                    if (c0 > row0)     s00 = -1e30f;
                    if (c0 + 1 > row0) s01 = -1e30f;
                    if (c0 > row1)     s10 = -1e30f;
                    if (c0 + 1 > row1) s11 = -1e30f;
                }
                cs[j][0] = s00; cs[j][1] = s01; cs[j][2] = s10; cs[j][3] = s11;
                mx0 = fmaxf(mx0, fmaxf(s00, s01));
                mx1 = fmaxf(mx1, fmaxf(s10, s11));
            }
            mx0 = fmaxf(mx0, __shfl_xor_sync(0xffffffffu, mx0, 1, 4));
            mx0 = fmaxf(mx0, __shfl_xor_sync(0xffffffffu, mx0, 2, 4));
            mx1 = fmaxf(mx1, __shfl_xor_sync(0xffffffffu, mx1, 1, 4));
            mx1 = fmaxf(mx1, __shfl_xor_sync(0xffffffffu, mx1, 2, 4));

            float mn0 = fmaxf(m0, mx0), mn1 = fmaxf(m1, mx1);
            float cr0 = __expf(m0 - mn0), cr1 = __expf(m1 - mn1);
            m0 = mn0; m1 = mn1;

            float sum0 = 0.f, sum1 = 0.f;
#pragma unroll
            for (int j = 0; j < 8; j++) {
                float p00 = __expf(cs[j][0] - mn0), p01 = __expf(cs[j][1] - mn0);
                float p10 = __expf(cs[j][2] - mn1), p11 = __expf(cs[j][3] - mn1);
                sum0 += p00 + p01; sum1 += p10 + p11;
                *(__half2*)&Ps[g * PST + 8 * j + 2 * q4]       = __floats2half2_rn(p00, p01);
                *(__half2*)&Ps[(g + 8) * PST + 8 * j + 2 * q4] = __floats2half2_rn(p10, p11);
            }
            sum0 += __shfl_xor_sync(0xffffffffu, sum0, 1, 4);
            sum0 += __shfl_xor_sync(0xffffffffu, sum0, 2, 4);
            sum1 += __shfl_xor_sync(0xffffffffu, sum1, 1, 4);
            sum1 += __shfl_xor_sync(0xffffffffu, sum1, 2, 4);
            l0 = l0 * cr0 + sum0;
            l1 = l1 * cr1 + sum1;

            if (!__all_sync(0xffffffffu, (cr0 == 1.f) & (cr1 == 1.f))) {
#pragma unroll
                for (int j = 0; j < 24; j++) {
                    co[j][0] *= cr0; co[j][1] *= cr0;
                    co[j][2] *= cr1; co[j][3] *= cr1;
                }
            }
            __syncwarp();

            // ---- O += P V : 4 + 48 ldsm4 + 96 mma ----
#pragma unroll
            for (int kc = 0; kc < 4; kc++) {
                uint32_t a[4];
                ldsm4(a[0], a[1], a[2], a[3], psa + (uint32_t)(kc * 16) * 2);
#pragma unroll
                for (int jp = 0; jp < 12; jp++) {
                    uint32_t b0, b1, b2, b3;
                    ldsm4(b0, b1, b2, b3, vtb + (uint32_t)(jp * 16 * VST + kc * 16) * 2);
                    mma16(co[2 * jp], a, b0, b1);
                    mma16(co[2 * jp + 1], a, b2, b3);
                }
            }
        }
    }

    const float i0 = 1.f / l0, i1 = 1.f / l1;
    float* O0 = O + ((size_t)b * TT + row0) * DD + d0base;
    float* O1 = O + ((size_t)b * TT + row1) * DD + d0base;
#pragma unroll
    for (int j = 0; j < 24; j++) {
        *(float2*)&O0[8 * j + 2 * q4] = make_float2(co[j][0] * i0, co[j][1] * i0);
        *(float2*)&O1[8 * j + 2 * q4] = make_float2(co[j][2] * i1, co[j][3] * i1);
    }
}

extern "C" void kernel_launch(void* const* d_in, const int* in_sizes, int n_in,
                              void* d_out, int out_size)
{
    const float* x  = (const float*)d_in[0];
    const float* Wk = (const float*)d_in[1];
    const float* Wq = (const float*)d_in[2];
    const float* Wv = (const float*)d_in[3];
    float* out = (float*)d_out;

    // fp32 -> fp16 (0.125 folded into Wq; exact power-of-2). Destinations are
    // device symbols resolved inside the kernel (which selector), NOT host-side.
    const int nx4 = BB * TT * DD / 4, nw4 = HD * DD / 4, nv4 = DD * DD / 4;
    to_half<<<(nx4 + 255) / 256, 256>>>(x, nx4, 1.f, 0);
    to_half<<<(nw4 + 255) / 256, 256>>>(Wq, nw4, 0.125f, 1);
    to_half<<<(nw4 + 255) / 256, 256>>>(Wk, nw4, 1.f, 2);
    to_half<<<(nv4 + 255) / 256, 256>>>(Wv, nv4, 1.f, 3);

    cudaFuncSetAttribute(proj_gemm, cudaFuncAttributeMaxDynamicSharedMemorySize, PROJ_SMEM_BYTES);
    proj_gemm<<<dim3(1, 128, 2), 256, PROJ_SMEM_BYTES>>>(0);
    proj_gemm<<<dim3(6, 128, 1), 256, PROJ_SMEM_BYTES>>>(2);

    cudaFuncSetAttribute(flash2, cudaFuncAttributeMaxDynamicSharedMemorySize, SMEM_BYTES);
    flash2<<<dim3(TT / BQ, BB), 256, SMEM_BYTES>>>(out);
}